// round 10
// baseline (speedup 1.0000x reference)
#include <cuda_runtime.h>

typedef unsigned int u32;
typedef unsigned long long u64;

#define TPB 512

// smem byte offsets (1 CTA, 2 windows)
#define XQ_OFF 0                          // X -> Q -> attn-out A tile: 128 x 132
#define KS_OFF 67584                      // K: 112 x 132 (win w at rows w*56, valid 49)
#define VS_OFF 126720                     // V: 112 x 132
#define SMB    185856
// P tiles: [win][head] 64 x 60 fp32/tf32, offset (win*4+h)*15360, ends 122880 (< VS_OFF)
// (P overlaps XQ+KS; safe: all Q/K reads complete before softmax stores P)

// pre-packed B fragments: [phase q,k,v,proj][ntile 16][kstep 16][lane 32] -> u64(b0,b1)
__device__ u64 g_B[4 * 8192];
// expanded rel-pos bias in S-fragment order: [cls=h2*2+msel][fidx=nt*2+mt][lane] -> float4
__device__ float4 g_bias4[8 * 14 * 32];

__device__ __forceinline__ u32 cvt_tf32(float f) {
    u32 u; asm("cvt.rna.tf32.f32 %0, %1;" : "=r"(u) : "f"(f)); return u;
}

__global__ void repack(const float* __restrict__ qw, const float* __restrict__ pw,
                       const float* __restrict__ bt)
{
    int i = blockIdx.x * 256 + threadIdx.x;
    if (i < 32768) {
        int phase = i >> 13;
        int rem   = i & 8191;
        int nt    = rem >> 9;
        int ks    = (rem >> 5) & 15;
        int lane  = rem & 31;
        int k0 = ks * 8 + (lane & 3);
        int n  = nt * 8 + (lane >> 2);
        float f0, f1;
        if (phase < 3) { f0 = qw[k0 * 384 + phase * 128 + n]; f1 = qw[(k0 + 4) * 384 + phase * 128 + n]; }
        else           { f0 = pw[k0 * 128 + n];               f1 = pw[(k0 + 4) * 128 + n]; }
        g_B[i] = ((u64)cvt_tf32(f1) << 32) | (u64)cvt_tf32(f0);
    } else if (i < 32768 + 3584) {
        int j4   = i - 32768;              // float4 index
        int cls  = j4 / 448;               // h2*2 + msel
        int rem  = j4 - cls * 448;
        int fidx = rem >> 5;               // nt*2 + mt
        int lane = rem & 31;
        int h2 = cls >> 1, msel = cls & 1;
        int nt = fidx >> 1, mt = fidx & 1;
        float v4[4];
        #pragma unroll
        for (int v = 0; v < 4; v++) {
            int row = msel * 32 + mt * 16 + (lane >> 2) + ((v >> 1) ? 8 : 0);
            int col = nt * 8 + (lane & 3) * 2 + (v & 1);
            if (col >= 49) v4[v] = -1e30f;     // padded key col -> p = 0
            else {
                int r = min(row, 48);
                int iy = r / 7, ix = r - iy * 7, jy = col / 7, jx = col - jy * 7;
                v4[v] = bt[((iy - jy + 6) * 13 + (ix - jx + 6)) * 4 + h2];
            }
        }
        g_bias4[j4] = make_float4(v4[0], v4[1], v4[2], v4[3]);
    }
}

// ---------------- helpers ----------------
__device__ __forceinline__ u32 lds32(u32 a) {
    u32 v; asm volatile("ld.shared.b32 %0, [%1];" : "=r"(v) : "r"(a)); return v;
}
__device__ __forceinline__ void sts32z(u32 a) {
    asm volatile("st.shared.b32 [%0], %1;" :: "r"(a), "r"(0u) : "memory");
}
__device__ __forceinline__ void sts64u(u32 a, u32 x, u32 y) {
    asm volatile("st.shared.v2.b32 [%0], {%1,%2};" :: "r"(a), "r"(x), "r"(y) : "memory");
}
__device__ __forceinline__ void sts128(u32 a, u32 x, u32 y, u32 z, u32 w) {
    asm volatile("st.shared.v4.b32 [%0], {%1,%2,%3,%4};" :: "r"(a), "r"(x), "r"(y), "r"(z), "r"(w) : "memory");
}
__device__ __forceinline__ void ldgB(u32& b0, u32& b1, const u64* p) {
    asm volatile("ld.global.nc.v2.u32 {%0,%1}, [%2];" : "=r"(b0), "=r"(b1) : "l"(p));
}
__device__ __forceinline__ void mma8(float c[4], const u32 a[4], u32 b0, u32 b1) {
    asm("mma.sync.aligned.m16n8k8.row.col.f32.tf32.tf32.f32 "
        "{%0,%1,%2,%3},{%4,%5,%6,%7},{%8,%9},{%0,%1,%2,%3};"
        : "+f"(c[0]), "+f"(c[1]), "+f"(c[2]), "+f"(c[3])
        : "r"(a[0]), "r"(a[1]), "r"(a[2]), "r"(a[3]), "r"(b0), "r"(b1));
}

// D[128x128] = A[128x128]·B ; warp tile m64 x n32 (8 warps: 2m x 4n)
__device__ __forceinline__ void gemm128(u32 As_addr, const u64* __restrict__ Bp,
                                        int mrow, int ncol, int lane, float acc[4][4][4])
{
    const int lq = lane >> 2, lr = lane & 3;
    const int ncg = ncol >> 3;
    #pragma unroll
    for (int ks = 0; ks < 16; ks++) {
        u32 a[4][4];
        #pragma unroll
        for (int mt = 0; mt < 4; mt++) {
            u32 ap = As_addr + (u32)(((mrow + mt * 16 + lq) * 132 + ks * 8 + lr) * 4);
            a[mt][0] = lds32(ap);
            a[mt][1] = lds32(ap + 8 * 132 * 4);
            a[mt][2] = lds32(ap + 16);
            a[mt][3] = lds32(ap + 8 * 132 * 4 + 16);
        }
        u32 b0[4], b1[4];
        #pragma unroll
        for (int nt = 0; nt < 4; nt++)
            ldgB(b0[nt], b1[nt], Bp + (((ncg + nt) * 16 + ks) * 32 + lane));
        #pragma unroll
        for (int mt = 0; mt < 4; mt++)
            #pragma unroll
            for (int nt = 0; nt < 4; nt++)
                mma8(acc[mt][nt], a[mt], b0[nt], b1[nt]);
    }
}

// store D rows to smem tile: D row r -> window r>>6, token r&63 (<49) at win*wstride+tok
__device__ __forceinline__ void store_kv(float acc[4][4][4], u32 dst, const float* __restrict__ bias,
                                         int mrow, int ncol, int lane, int wstride)
{
    const int lq = lane >> 2, lr = lane & 3;
    #pragma unroll
    for (int nt = 0; nt < 4; nt++) {
        const int c = ncol + nt * 8 + lr * 2;
        const float blo = __ldg(bias + c), bhi = __ldg(bias + c + 1);
        #pragma unroll
        for (int mt = 0; mt < 4; mt++) {
            #pragma unroll
            for (int half = 0; half < 2; half++) {
                const int r = mrow + mt * 16 + lq + half * 8;
                const int win = r >> 6, tok = r & 63;
                if (tok < 49)
                    sts64u(dst + (u32)(((win * wstride + tok) * 132 + c) * 4),
                           cvt_tf32(acc[mt][nt][2 * half] + blo),
                           cvt_tf32(acc[mt][nt][2 * half + 1] + bhi));
            }
        }
    }
}

__global__ __launch_bounds__(TPB, 1)
void win_attn_kernel(const float* __restrict__ x,
                     const float* __restrict__ qkv_b,
                     const float* __restrict__ proj_b,
                     float* __restrict__ out)
{
    extern __shared__ char smem[];
    const u32 sbase = (u32)__cvta_generic_to_shared(smem);
    const u32 XQ_a = sbase + XQ_OFF;
    const u32 KS_a = sbase + KS_OFF;
    const u32 VS_a = sbase + VS_OFF;

    const int t    = threadIdx.x;
    const int wid  = t >> 5;
    const int lane = t & 31;
    const int lq   = lane >> 2, lr = lane & 3;
    const int pidx = blockIdx.x;           // window pair

    // ---- stage X (2 windows x 49 rows) as tf32 into XQ (win w at rows w*64) ----
    for (int idx = t; idx < 98 * 32; idx += TPB) {
        int r = idx >> 5, c4 = idx & 31;
        int wsel = (r >= 49);
        int tok  = r - wsel * 49;
        int win  = pidx * 2 + wsel;
        int b = win >> 6, ww = win & 63, wy = ww >> 3, wx = ww & 7;
        int iy = tok / 7, ix = tok - iy * 7;
        const float4 v = *(const float4*)(x + ((long)((b * 56 + wy * 7 + iy) * 56 + wx * 7 + ix)) * 128 + c4 * 4);
        sts128(XQ_a + (u32)(((wsel * 64 + tok) * 132 + c4 * 4) * 4),
               cvt_tf32(v.x), cvt_tf32(v.y), cvt_tf32(v.z), cvt_tf32(v.w));
    }
    // zero XQ pad rows (win*64+49..63): 2 wins x 15 rows x 132 = 3960 words
    for (int i = t; i < 3960; i += TPB) {
        int wsel = i / 1980, rem = i - wsel * 1980;
        int rr = rem / 132, cc = rem - rr * 132;
        sts32z(XQ_a + (u32)(((wsel * 64 + 49 + rr) * 132 + cc) * 4));
    }
    // zero K/V pad rows (rows win*56+49..55): 2 tiles x 2 wins x 7 rows x 132 = 3696
    for (int i = t; i < 3696; i += TPB) {
        int tile = i / 1848, rem = i - tile * 1848;
        int wsel = rem / 924, rem2 = rem - wsel * 924;
        int rr = rem2 / 132, cc = rem2 - rr * 132;
        sts32z(sbase + (tile ? VS_OFF : KS_OFF) + (u32)(((wsel * 56 + 49 + rr) * 132 + cc) * 4));
    }
    __syncthreads();

    const bool gw  = (wid < 8);
    const int mrow = ((wid >> 2) & 1) * 64;
    const int ncol = (wid & 3) * 32;

    float qacc[4][4][4];
    if (gw) {
        float acc[4][4][4];
        #pragma unroll
        for (int a = 0; a < 4; a++) for (int q = 0; q < 4; q++) for (int c = 0; c < 4; c++) acc[a][q][c] = 0.f;
        gemm128(XQ_a, g_B + 1 * 8192, mrow, ncol, lane, acc);
        store_kv(acc, KS_a, qkv_b + 128, mrow, ncol, lane, 56);
        #pragma unroll
        for (int a = 0; a < 4; a++) for (int q = 0; q < 4; q++) for (int c = 0; c < 4; c++) acc[a][q][c] = 0.f;
        gemm128(XQ_a, g_B + 2 * 8192, mrow, ncol, lane, acc);
        store_kv(acc, VS_a, qkv_b + 256, mrow, ncol, lane, 56);
        #pragma unroll
        for (int a = 0; a < 4; a++) for (int q = 0; q < 4; q++) for (int c = 0; c < 4; c++) qacc[a][q][c] = 0.f;
        gemm128(XQ_a, g_B + 0 * 8192, mrow, ncol, lane, qacc);
    }
    __syncthreads();                       // all A-reads of X complete
    if (gw) store_kv(qacc, XQ_a, qkv_b, mrow, ncol, lane, 64);
    __syncthreads();

    // ================= attention: warp = (win, head, m-half) =================
    const int awin = wid >> 3;
    const int h2   = (wid >> 1) & 3;
    const int msel = wid & 1;
    const int mra  = awin * 64 + msel * 32;     // XQ row base
    const int mloc = msel * 32;                 // P-local row base
    const int kb   = awin * 56;                 // K/V row base
    const u32 P_a  = sbase + (u32)((awin * 4 + h2) * 15360);   // 64 x 60
    const int cls  = h2 * 2 + msel;
    const float scale = 0.17677669529663687f;   // 32^-0.5

    // ---- S = Q·K^T  (m32 x n56, K=32) ----
    float sacc[2][7][4];
    #pragma unroll
    for (int a = 0; a < 2; a++) for (int q = 0; q < 7; q++) for (int c = 0; c < 4; c++) sacc[a][q][c] = 0.f;
    #pragma unroll
    for (int ks = 0; ks < 4; ks++) {
        u32 a[2][4];
        #pragma unroll
        for (int mt = 0; mt < 2; mt++) {
            u32 ap = XQ_a + (u32)(((mra + mt * 16 + lq) * 132 + h2 * 32 + ks * 8 + lr) * 4);
            a[mt][0] = lds32(ap);
            a[mt][1] = lds32(ap + 8 * 132 * 4);
            a[mt][2] = lds32(ap + 16);
            a[mt][3] = lds32(ap + 8 * 132 * 4 + 16);
        }
        #pragma unroll
        for (int nt = 0; nt < 7; nt++) {
            u32 bp = KS_a + (u32)(((kb + nt * 8 + lq) * 132 + h2 * 32 + ks * 8 + lr) * 4);
            u32 b0 = lds32(bp), b1 = lds32(bp + 16);
            mma8(sacc[0][nt], a[0], b0, b1);
            mma8(sacc[1][nt], a[1], b0, b1);
        }
    }
    __syncthreads();                       // Q/K reads done before P overwrites region

    // ---- softmax (bias pre-expanded in fragment order; padded cols -1e30) ----
    float part[4] = {0.f, 0.f, 0.f, 0.f};
    #pragma unroll
    for (int nt = 0; nt < 7; nt++) {
        #pragma unroll
        for (int mt = 0; mt < 2; mt++) {
            const float4 gb = __ldg(g_bias4 + (cls * 14 + nt * 2 + mt) * 32 + lane);
            float p0 = __expf(fmaf(sacc[mt][nt][0], scale, gb.x));
            float p1 = __expf(fmaf(sacc[mt][nt][1], scale, gb.y));
            float p2 = __expf(fmaf(sacc[mt][nt][2], scale, gb.z));
            float p3 = __expf(fmaf(sacc[mt][nt][3], scale, gb.w));
            part[2 * mt]     += p0 + p1;
            part[2 * mt + 1] += p2 + p3;
            const int r0 = mloc + mt * 16 + lq, col0 = nt * 8 + 2 * lr;
            sts64u(P_a + (u32)((r0 * 60 + col0) * 4), cvt_tf32(p0), cvt_tf32(p1));
            sts64u(P_a + (u32)(((r0 + 8) * 60 + col0) * 4), cvt_tf32(p2), cvt_tf32(p3));
        }
    }
    __syncwarp();                          // P rows for this msel half are warp-private
    float inv[4];
    #pragma unroll
    for (int s = 0; s < 4; s++) {
        float l = part[s];
        l += __shfl_xor_sync(0xffffffffu, l, 1);
        l += __shfl_xor_sync(0xffffffffu, l, 2);
        inv[s] = 1.f / l;
    }

    // ---- O = P·V  (m32 x n32, K=56) ----
    float oacc[2][4][4];
    #pragma unroll
    for (int a = 0; a < 2; a++) for (int q = 0; q < 4; q++) for (int c = 0; c < 4; c++) oacc[a][q][c] = 0.f;
    #pragma unroll
    for (int ks = 0; ks < 7; ks++) {
        u32 a[2][4];
        #pragma unroll
        for (int mt = 0; mt < 2; mt++) {
            u32 ap = P_a + (u32)(((mloc + mt * 16 + lq) * 60 + ks * 8 + lr) * 4);
            a[mt][0] = lds32(ap);
            a[mt][1] = lds32(ap + 8 * 60 * 4);
            a[mt][2] = lds32(ap + 16);
            a[mt][3] = lds32(ap + 8 * 60 * 4 + 16);
        }
        #pragma unroll
        for (int nt = 0; nt < 4; nt++) {
            u32 bp = VS_a + (u32)((((kb + ks * 8 + lr) * 132) + h2 * 32 + nt * 8 + lq) * 4);
            u32 b0 = lds32(bp), b1 = lds32(bp + 4 * 132 * 4);
            mma8(oacc[0][nt], a[0], b0, b1);
            mma8(oacc[1][nt], a[1], b0, b1);
        }
    }
    __syncthreads();                       // all P·V reads done before O overwrites XQ/P

    // ---- O epilogue: normalize + tf32 into XQ (proj A tile) ----
    #pragma unroll
    for (int mt = 0; mt < 2; mt++) {
        #pragma unroll
        for (int nt = 0; nt < 4; nt++) {
            const int col = h2 * 32 + nt * 8 + 2 * lr;
            const u32 ra = XQ_a + (u32)(((mra + mt * 16 + lq) * 132 + col) * 4);
            sts64u(ra, cvt_tf32(oacc[mt][nt][0] * inv[2 * mt]),
                       cvt_tf32(oacc[mt][nt][1] * inv[2 * mt]));
            sts64u(ra + 8 * 132 * 4, cvt_tf32(oacc[mt][nt][2] * inv[2 * mt + 1]),
                                     cvt_tf32(oacc[mt][nt][3] * inv[2 * mt + 1]));
        }
    }
    __syncthreads();

    // ---- proj phase (8 warps) ----
    if (gw) {
        float acc[4][4][4];
        #pragma unroll
        for (int a = 0; a < 4; a++) for (int q = 0; q < 4; q++) for (int c = 0; c < 4; c++) acc[a][q][c] = 0.f;
        gemm128(XQ_a, g_B + 3 * 8192, mrow, ncol, lane, acc);

        #pragma unroll
        for (int nt = 0; nt < 4; nt++) {
            const int c = ncol + nt * 8 + lr * 2;
            const float blo = __ldg(proj_b + c), bhi = __ldg(proj_b + c + 1);
            #pragma unroll
            for (int mt = 0; mt < 4; mt++) {
                #pragma unroll
                for (int half = 0; half < 2; half++) {
                    const int r = mrow + mt * 16 + lq + half * 8;
                    const int wsel = r >> 6, tok = r & 63;
                    if (tok < 49) {
                        const int win = pidx * 2 + wsel;
                        const int b = win >> 6, ww = win & 63, wy = ww >> 3, wx = ww & 7;
                        const int iy = tok / 7, ix = tok - iy * 7;
                        float2 v;
                        v.x = acc[mt][nt][2 * half + 0] + blo;
                        v.y = acc[mt][nt][2 * half + 1] + bhi;
                        *(float2*)(out + ((long)((b * 56 + wy * 7 + iy) * 56 + wx * 7 + ix)) * 128 + c) = v;
                    }
                }
            }
        }
    }
}

extern "C" void kernel_launch(void* const* d_in, const int* in_sizes, int n_in,
                              void* d_out, int out_size)
{
    const float* x      = (const float*)d_in[0];
    const float* qkv_w  = (const float*)d_in[1];
    const float* qkv_b  = (const float*)d_in[2];
    const float* proj_w = (const float*)d_in[3];
    const float* proj_b = (const float*)d_in[4];
    const float* bt     = (const float*)d_in[5];
    float* out = (float*)d_out;

    repack<<<142, 256>>>(qkv_w, proj_w, bt);

    cudaFuncSetAttribute(win_attn_kernel,
                         cudaFuncAttributeMaxDynamicSharedMemorySize, SMB);
    win_attn_kernel<<<2048, TPB, SMB>>>(x, qkv_b, proj_b, out);
}

// round 11
// speedup vs baseline: 1.1837x; 1.1837x over previous
#include <cuda_runtime.h>

typedef unsigned int u32;
typedef unsigned long long u64;

#define TPB 256

// smem byte offsets (1 window/CTA)
#define XQ_OFF 0                          // X -> Q -> attn-out A tile: 64 x 132
#define KS_OFF 33792                      // K: 56 x 132 (valid rows 0..48, pad zeroed)
#define VS_OFF 63360                      // V: 56 x 132 (pad zeroed)
#define SMB    92928
// P tiles: [head] 64 x 60 fp32/tf32 at h*15360, ends 61440 (< VS_OFF)
// (P overlaps XQ+KS; safe: all Q/K reads complete before softmax stores P)

// pre-packed B fragments: [phase q,k,v,proj][ntile 16][kstep 16][lane 32] -> u64(b0,b1)
__device__ u64 g_B[4 * 8192];
// expanded rel-pos bias in S-fragment order: [cls=h2*2+msel][fidx=nt*2+mt][lane] -> float4
__device__ float4 g_bias4[8 * 14 * 32];

__device__ __forceinline__ u32 cvt_tf32(float f) {
    u32 u; asm("cvt.rna.tf32.f32 %0, %1;" : "=r"(u) : "f"(f)); return u;
}

__global__ void repack(const float* __restrict__ qw, const float* __restrict__ pw,
                       const float* __restrict__ bt)
{
    int i = blockIdx.x * 256 + threadIdx.x;
    if (i < 32768) {
        int phase = i >> 13;
        int rem   = i & 8191;
        int nt    = rem >> 9;
        int ks    = (rem >> 5) & 15;
        int lane  = rem & 31;
        int k0 = ks * 8 + (lane & 3);
        int n  = nt * 8 + (lane >> 2);
        float f0, f1;
        if (phase < 3) { f0 = qw[k0 * 384 + phase * 128 + n]; f1 = qw[(k0 + 4) * 384 + phase * 128 + n]; }
        else           { f0 = pw[k0 * 128 + n];               f1 = pw[(k0 + 4) * 128 + n]; }
        g_B[i] = ((u64)cvt_tf32(f1) << 32) | (u64)cvt_tf32(f0);
    } else if (i < 32768 + 3584) {
        int j4   = i - 32768;              // float4 index
        int cls  = j4 / 448;               // h2*2 + msel
        int rem  = j4 - cls * 448;
        int fidx = rem >> 5;               // nt*2 + mt
        int lane = rem & 31;
        int msel = cls & 1;
        int h2 = cls >> 1;
        int nt = fidx >> 1, mt = fidx & 1;
        float v4[4];
        #pragma unroll
        for (int v = 0; v < 4; v++) {
            int row = msel * 32 + mt * 16 + (lane >> 2) + ((v >> 1) ? 8 : 0);
            int col = nt * 8 + (lane & 3) * 2 + (v & 1);
            if (col >= 49) v4[v] = -1e30f;     // padded key col -> p = 0
            else {
                int r = min(row, 48);
                int iy = r / 7, ix = r - iy * 7, jy = col / 7, jx = col - jy * 7;
                v4[v] = bt[((iy - jy + 6) * 13 + (ix - jx + 6)) * 4 + h2];
            }
        }
        g_bias4[j4] = make_float4(v4[0], v4[1], v4[2], v4[3]);
    }
}

// ---------------- helpers ----------------
__device__ __forceinline__ u32 lds32(u32 a) {
    u32 v; asm volatile("ld.shared.b32 %0, [%1];" : "=r"(v) : "r"(a)); return v;
}
__device__ __forceinline__ void sts32z(u32 a) {
    asm volatile("st.shared.b32 [%0], %1;" :: "r"(a), "r"(0u) : "memory");
}
__device__ __forceinline__ void sts64u(u32 a, u32 x, u32 y) {
    asm volatile("st.shared.v2.b32 [%0], {%1,%2};" :: "r"(a), "r"(x), "r"(y) : "memory");
}
__device__ __forceinline__ void sts128(u32 a, u32 x, u32 y, u32 z, u32 w) {
    asm volatile("st.shared.v4.b32 [%0], {%1,%2,%3,%4};" :: "r"(a), "r"(x), "r"(y), "r"(z), "r"(w) : "memory");
}
__device__ __forceinline__ void ldgB(u32& b0, u32& b1, const u64* p) {
    asm volatile("ld.global.nc.v2.u32 {%0,%1}, [%2];" : "=r"(b0), "=r"(b1) : "l"(p));
}
__device__ __forceinline__ void mma8(float c[4], const u32 a[4], u32 b0, u32 b1) {
    asm("mma.sync.aligned.m16n8k8.row.col.f32.tf32.tf32.f32 "
        "{%0,%1,%2,%3},{%4,%5,%6,%7},{%8,%9},{%0,%1,%2,%3};"
        : "+f"(c[0]), "+f"(c[1]), "+f"(c[2]), "+f"(c[3])
        : "r"(a[0]), "r"(a[1]), "r"(a[2]), "r"(a[3]), "r"(b0), "r"(b1));
}

// D[64x128] = A[64x128]·B ; warp tile m32 x n32 (8 warps: 2m x 4n)
__device__ __forceinline__ void gemm64(u32 As_addr, const u64* __restrict__ Bp,
                                       int mrow, int ncol, int lane, float acc[2][4][4])
{
    const int lq = lane >> 2, lr = lane & 3;
    const int ncg = ncol >> 3;
    #pragma unroll
    for (int ks = 0; ks < 16; ks++) {
        u32 a[2][4];
        #pragma unroll
        for (int mt = 0; mt < 2; mt++) {
            u32 ap = As_addr + (u32)(((mrow + mt * 16 + lq) * 132 + ks * 8 + lr) * 4);
            a[mt][0] = lds32(ap);
            a[mt][1] = lds32(ap + 8 * 132 * 4);
            a[mt][2] = lds32(ap + 16);
            a[mt][3] = lds32(ap + 8 * 132 * 4 + 16);
        }
        u32 b0[4], b1[4];
        #pragma unroll
        for (int nt = 0; nt < 4; nt++)
            ldgB(b0[nt], b1[nt], Bp + (((ncg + nt) * 16 + ks) * 32 + lane));
        #pragma unroll
        for (int mt = 0; mt < 2; mt++)
            #pragma unroll
            for (int nt = 0; nt < 4; nt++)
                mma8(acc[mt][nt], a[mt], b0[nt], b1[nt]);
    }
}

// store K/V/Q tiles as tf32 (feed later mmas), rows < 49 only
__device__ __forceinline__ void store_kvq(float acc[2][4][4], u32 dst_addr,
                                          const float* __restrict__ bias,
                                          int mrow, int ncol, int lane)
{
    const int lq = lane >> 2, lr = lane & 3;
    #pragma unroll
    for (int nt = 0; nt < 4; nt++) {
        const int c = ncol + nt * 8 + lr * 2;
        const float blo = __ldg(bias + c), bhi = __ldg(bias + c + 1);
        #pragma unroll
        for (int mt = 0; mt < 2; mt++) {
            const int r = mrow + mt * 16 + lq;
            if (r < 49)
                sts64u(dst_addr + (u32)((r * 132 + c) * 4),
                       cvt_tf32(acc[mt][nt][0] + blo), cvt_tf32(acc[mt][nt][1] + bhi));
            if (r + 8 < 49)
                sts64u(dst_addr + (u32)(((r + 8) * 132 + c) * 4),
                       cvt_tf32(acc[mt][nt][2] + blo), cvt_tf32(acc[mt][nt][3] + bhi));
        }
    }
}

__global__ __launch_bounds__(TPB, 2)
void win_attn_kernel(const float* __restrict__ x,
                     const float* __restrict__ qkv_b,
                     const float* __restrict__ proj_b,
                     float* __restrict__ out)
{
    extern __shared__ char smem[];
    const u32 sbase = (u32)__cvta_generic_to_shared(smem);
    const u32 XQ_a = sbase + XQ_OFF;
    const u32 KS_a = sbase + KS_OFF;
    const u32 VS_a = sbase + VS_OFF;

    const int t    = threadIdx.x;
    const int wid  = t >> 5;
    const int lane = t & 31;
    const int lq   = lane >> 2, lr = lane & 3;
    const int mrow = (wid >> 2) * 32;      // linear-gemm m tile
    const int ncol = (wid & 3) * 32;       // linear-gemm n tile

    const int blk = blockIdx.x;
    const int b   = blk >> 6;
    const int win = blk & 63;
    const int wy  = win >> 3;
    const int wx  = win & 7;
    const long base = (((long)b * 56 + wy * 7) * 56 + wx * 7) * 128;

    // zero K and V padding rows 49..55 (finite S for padded cols; 0*V harmless)
    for (int i = t; i < 1848; i += TPB) {
        int tile = i / 924, rem = i - tile * 924;
        int rr = rem / 132, cc = rem - rr * 132;
        sts32z(sbase + (tile ? VS_OFF : KS_OFF) + (u32)(((49 + rr) * 132 + cc) * 4));
    }

    // stage X (49x128) as tf32 into XQ
    for (int idx = t; idx < 49 * 32; idx += TPB) {
        int r  = idx >> 5;
        int c4 = idx & 31;
        int iy = r / 7, ix = r - iy * 7;
        const float4 v = *(const float4*)(x + base + ((long)iy * 56 + ix) * 128 + c4 * 4);
        sts128(XQ_a + (u32)((r * 132 + c4 * 4) * 4),
               cvt_tf32(v.x), cvt_tf32(v.y), cvt_tf32(v.z), cvt_tf32(v.w));
    }
    __syncthreads();

    // ---- K phase ----
    {
        float acc[2][4][4];
        #pragma unroll
        for (int a = 0; a < 2; a++) for (int q = 0; q < 4; q++) for (int c = 0; c < 4; c++) acc[a][q][c] = 0.f;
        gemm64(XQ_a, g_B + 1 * 8192, mrow, ncol, lane, acc);
        store_kvq(acc, KS_a, qkv_b + 128, mrow, ncol, lane);
    }
    // ---- V phase ----
    {
        float acc[2][4][4];
        #pragma unroll
        for (int a = 0; a < 2; a++) for (int q = 0; q < 4; q++) for (int c = 0; c < 4; c++) acc[a][q][c] = 0.f;
        gemm64(XQ_a, g_B + 2 * 8192, mrow, ncol, lane, acc);
        store_kvq(acc, VS_a, qkv_b + 256, mrow, ncol, lane);
    }
    // ---- Q phase (overwrites XQ after CTA-wide read completion) ----
    {
        float acc[2][4][4];
        #pragma unroll
        for (int a = 0; a < 2; a++) for (int q = 0; q < 4; q++) for (int c = 0; c < 4; c++) acc[a][q][c] = 0.f;
        gemm64(XQ_a, g_B + 0 * 8192, mrow, ncol, lane, acc);
        __syncthreads();
        store_kvq(acc, XQ_a, qkv_b, mrow, ncol, lane);
    }
    __syncthreads();

    // ================= attention via mma: warp = (head h2, m-half msel) =================
    const int h2   = wid >> 1;
    const int msel = wid & 1;
    const int mra  = msel * 32;
    const u32 P_a  = sbase + (u32)(h2 * 15360);    // 64 x 60 fp32/tf32, stride 60
    const int cls  = wid;                          // h2*2 + msel
    const float scale = 0.17677669529663687f;      // 32^-0.5

    // ---- S = Q·K^T  (M=32 rows, N=56 cols, K=32) ----
    float sacc[2][7][4];
    #pragma unroll
    for (int a = 0; a < 2; a++) for (int q = 0; q < 7; q++) for (int c = 0; c < 4; c++) sacc[a][q][c] = 0.f;
    #pragma unroll
    for (int ks = 0; ks < 4; ks++) {
        u32 a[2][4];
        #pragma unroll
        for (int mt = 0; mt < 2; mt++) {
            u32 ap = XQ_a + (u32)(((mra + mt * 16 + lq) * 132 + h2 * 32 + ks * 8 + lr) * 4);
            a[mt][0] = lds32(ap);
            a[mt][1] = lds32(ap + 8 * 132 * 4);
            a[mt][2] = lds32(ap + 16);
            a[mt][3] = lds32(ap + 8 * 132 * 4 + 16);
        }
        #pragma unroll
        for (int nt = 0; nt < 7; nt++) {
            u32 bp = KS_a + (u32)(((nt * 8 + lq) * 132 + h2 * 32 + ks * 8 + lr) * 4);
            u32 b0 = lds32(bp), b1 = lds32(bp + 16);
            mma8(sacc[0][nt], a[0], b0, b1);
            mma8(sacc[1][nt], a[1], b0, b1);
        }
    }
    __syncthreads();   // all warps done reading Q/K before P overwrites that region

    // ---- softmax (bias pre-expanded in fragment order; padded cols -1e30) ----
    float part[4] = {0.f, 0.f, 0.f, 0.f};
    #pragma unroll
    for (int nt = 0; nt < 7; nt++) {
        #pragma unroll
        for (int mt = 0; mt < 2; mt++) {
            const float4 gb = __ldg(g_bias4 + (cls * 14 + nt * 2 + mt) * 32 + lane);
            float p0 = __expf(fmaf(sacc[mt][nt][0], scale, gb.x));
            float p1 = __expf(fmaf(sacc[mt][nt][1], scale, gb.y));
            float p2 = __expf(fmaf(sacc[mt][nt][2], scale, gb.z));
            float p3 = __expf(fmaf(sacc[mt][nt][3], scale, gb.w));
            part[2 * mt]     += p0 + p1;
            part[2 * mt + 1] += p2 + p3;
            const int r0 = mra + mt * 16 + lq, col0 = nt * 8 + 2 * lr;
            sts64u(P_a + (u32)((r0 * 60 + col0) * 4), cvt_tf32(p0), cvt_tf32(p1));
            sts64u(P_a + (u32)(((r0 + 8) * 60 + col0) * 4), cvt_tf32(p2), cvt_tf32(p3));
        }
    }
    __syncwarp();      // cross-lane visibility of this warp's P stores
    float inv[4];
    #pragma unroll
    for (int s = 0; s < 4; s++) {
        float l = part[s];
        l += __shfl_xor_sync(0xffffffffu, l, 1);
        l += __shfl_xor_sync(0xffffffffu, l, 2);
        inv[s] = 1.f / l;
    }

    // ---- O = P·V  (M=32 rows, N=32 dims, K=56) ----
    float oacc[2][4][4];
    #pragma unroll
    for (int a = 0; a < 2; a++) for (int q = 0; q < 4; q++) for (int c = 0; c < 4; c++) oacc[a][q][c] = 0.f;
    #pragma unroll
    for (int ks = 0; ks < 7; ks++) {
        u32 a[2][4];
        #pragma unroll
        for (int mt = 0; mt < 2; mt++) {
            u32 ap = P_a + (u32)(((mra + mt * 16 + lq) * 60 + ks * 8 + lr) * 4);
            a[mt][0] = lds32(ap);
            a[mt][1] = lds32(ap + 8 * 60 * 4);
            a[mt][2] = lds32(ap + 16);
            a[mt][3] = lds32(ap + 8 * 60 * 4 + 16);
        }
        #pragma unroll
        for (int nt = 0; nt < 4; nt++) {
            u32 bp = VS_a + (u32)((((ks * 8 + lr) * 132) + h2 * 32 + nt * 8 + lq) * 4);
            u32 b0 = lds32(bp), b1 = lds32(bp + 4 * 132 * 4);
            mma8(oacc[0][nt], a[0], b0, b1);
            mma8(oacc[1][nt], a[1], b0, b1);
        }
    }
    __syncthreads();   // all P·V reads done before O overwrites XQ/P region

    // ---- O epilogue: normalize, cvt tf32, store as proj A tile ----
    #pragma unroll
    for (int mt = 0; mt < 2; mt++) {
        #pragma unroll
        for (int nt = 0; nt < 4; nt++) {
            const int col = h2 * 32 + nt * 8 + 2 * lr;
            const u32 ra = XQ_a + (u32)(((mra + mt * 16 + lq) * 132 + col) * 4);
            sts64u(ra, cvt_tf32(oacc[mt][nt][0] * inv[2 * mt]),
                       cvt_tf32(oacc[mt][nt][1] * inv[2 * mt]));
            sts64u(ra + 8 * 132 * 4, cvt_tf32(oacc[mt][nt][2] * inv[2 * mt + 1]),
                                     cvt_tf32(oacc[mt][nt][3] * inv[2 * mt + 1]));
        }
    }
    __syncthreads();

    // ---- proj phase ----
    {
        float acc[2][4][4];
        #pragma unroll
        for (int a = 0; a < 2; a++) for (int q = 0; q < 4; q++) for (int c = 0; c < 4; c++) acc[a][q][c] = 0.f;
        gemm64(XQ_a, g_B + 3 * 8192, mrow, ncol, lane, acc);

        #pragma unroll
        for (int nt = 0; nt < 4; nt++) {
            const int c = ncol + nt * 8 + lr * 2;
            const float blo = __ldg(proj_b + c), bhi = __ldg(proj_b + c + 1);
            #pragma unroll
            for (int mt = 0; mt < 2; mt++) {
                #pragma unroll
                for (int half = 0; half < 2; half++) {
                    const int r = mrow + mt * 16 + lq + half * 8;
                    if (r < 49) {
                        const int iy = r / 7, ix = r - iy * 7;
                        float2 v;
                        v.x = acc[mt][nt][2 * half + 0] + blo;
                        v.y = acc[mt][nt][2 * half + 1] + bhi;
                        *(float2*)(out + base + ((long)iy * 56 + ix) * 128 + c) = v;
                    }
                }
            }
        }
    }
}

extern "C" void kernel_launch(void* const* d_in, const int* in_sizes, int n_in,
                              void* d_out, int out_size)
{
    const float* x      = (const float*)d_in[0];
    const float* qkv_w  = (const float*)d_in[1];
    const float* qkv_b  = (const float*)d_in[2];
    const float* proj_w = (const float*)d_in[3];
    const float* proj_b = (const float*)d_in[4];
    const float* bt     = (const float*)d_in[5];
    float* out = (float*)d_out;

    repack<<<142, 256>>>(qkv_w, proj_w, bt);

    cudaFuncSetAttribute(win_attn_kernel,
                         cudaFuncAttributeMaxDynamicSharedMemorySize, SMB);
    win_attn_kernel<<<4096, TPB, SMB>>>(x, qkv_b, proj_b, out);
}

// round 13
// speedup vs baseline: 1.7678x; 1.4935x over previous
#include <cuda_runtime.h>

typedef unsigned int u32;
typedef unsigned long long u64;

#define TPB 256

// smem byte offsets (fp16 tiles)
#define XQ_OFF 0            // X -> Q -> attn-out: fp16 64 rows x 136 (272B stride)
#define KS_OFF 17408        // K: fp16 56 x 136 (pad rows 49..55 zeroed)
#define VT_OFF 32640        // V^T: fp16 128 dims x 72 toks (144B stride; toks 48..71 words zeroed)
#define P_OFF  51072        // P: fp16 per-head 64 x 72 (144B stride), 4 heads x 9216B
#define SMB    87936

// pre-packed fp16 B fragments: [phase q,k,v,proj][ntile 16][kstep 8 (k16)][lane 32] -> u64(b0,b1)
__device__ u64 g_B[4 * 4096];
// expanded rel-pos bias in S-fragment order: [cls=h2*2+msel][fidx=nt*2+mt][lane] -> float4
__device__ float4 g_bias4[8 * 14 * 32];

// pack two f32 -> f16x2 (lo = first arg)
__device__ __forceinline__ u32 pack_h2(float lo, float hi) {
    u32 d; asm("cvt.rn.f16x2.f32 %0, %1, %2;" : "=r"(d) : "f"(hi), "f"(lo)); return d;
}

__global__ void repack(const float* __restrict__ qw, const float* __restrict__ pw,
                       const float* __restrict__ bt)
{
    int i = blockIdx.x * 256 + threadIdx.x;
    if (i < 16384) {
        int phase = i >> 12;
        int rem   = i & 4095;
        int nt    = rem >> 8;
        int ks    = (rem >> 5) & 7;
        int lane  = rem & 31;
        int n  = nt * 8 + (lane >> 2);
        int k0 = ks * 16 + (lane & 3) * 2;
        float f00, f01, f10, f11;
        if (phase < 3) {
            f00 = qw[(k0    ) * 384 + phase * 128 + n];
            f01 = qw[(k0 + 1) * 384 + phase * 128 + n];
            f10 = qw[(k0 + 8) * 384 + phase * 128 + n];
            f11 = qw[(k0 + 9) * 384 + phase * 128 + n];
        } else {
            f00 = pw[(k0    ) * 128 + n];
            f01 = pw[(k0 + 1) * 128 + n];
            f10 = pw[(k0 + 8) * 128 + n];
            f11 = pw[(k0 + 9) * 128 + n];
        }
        u32 b0 = pack_h2(f00, f01), b1 = pack_h2(f10, f11);
        g_B[i] = ((u64)b1 << 32) | (u64)b0;
    } else if (i < 16384 + 3584) {
        int j4   = i - 16384;              // float4 index
        int cls  = j4 / 448;               // h2*2 + msel
        int rem  = j4 - cls * 448;
        int fidx = rem >> 5;               // nt*2 + mt
        int lane = rem & 31;
        int msel = cls & 1;
        int h2 = cls >> 1;
        int nt = fidx >> 1, mt = fidx & 1;
        float v4[4];
        #pragma unroll
        for (int v = 0; v < 4; v++) {
            int row = msel * 32 + mt * 16 + (lane >> 2) + ((v >> 1) ? 8 : 0);
            int col = nt * 8 + (lane & 3) * 2 + (v & 1);
            if (col >= 49) v4[v] = -1e30f;     // padded key col -> p = 0
            else {
                int r = min(row, 48);
                int iy = r / 7, ix = r - iy * 7, jy = col / 7, jx = col - jy * 7;
                v4[v] = bt[((iy - jy + 6) * 13 + (ix - jx + 6)) * 4 + h2];
            }
        }
        g_bias4[j4] = make_float4(v4[0], v4[1], v4[2], v4[3]);
    }
}

// ---------------- helpers ----------------
__device__ __forceinline__ u32 lds32(u32 a) {
    u32 v; asm volatile("ld.shared.b32 %0, [%1];" : "=r"(v) : "r"(a)); return v;
}
__device__ __forceinline__ void sts32(u32 a, u32 v) {
    asm volatile("st.shared.b32 [%0], %1;" :: "r"(a), "r"(v) : "memory");
}
__device__ __forceinline__ void sts16(u32 a, u32 v) {
    asm volatile("st.shared.u16 [%0], %1;" :: "r"(a), "r"(v) : "memory");
}
__device__ __forceinline__ void sts64u(u32 a, u32 x, u32 y) {
    asm volatile("st.shared.v2.b32 [%0], {%1,%2};" :: "r"(a), "r"(x), "r"(y) : "memory");
}
__device__ __forceinline__ void ldgB(u32& b0, u32& b1, const u64* p) {
    asm volatile("ld.global.nc.v2.u32 {%0,%1}, [%2];" : "=r"(b0), "=r"(b1) : "l"(p));
}
__device__ __forceinline__ void mma16(float c[4], const u32 a[4], u32 b0, u32 b1) {
    asm("mma.sync.aligned.m16n8k16.row.col.f32.f16.f16.f32 "
        "{%0,%1,%2,%3},{%4,%5,%6,%7},{%8,%9},{%0,%1,%2,%3};"
        : "+f"(c[0]), "+f"(c[1]), "+f"(c[2]), "+f"(c[3])
        : "r"(a[0]), "r"(a[1]), "r"(a[2]), "r"(a[3]), "r"(b0), "r"(b1));
}

// D[64x128] = A[64x128]·B ; A = fp16 smem tile, stride 272B; warp tile m32 x n32
__device__ __forceinline__ void gemm64h(u32 As_addr, const u64* __restrict__ Bp,
                                        int mrow, int ncol, int lane, float acc[2][4][4])
{
    const int lq = lane >> 2, lr = lane & 3;
    const int ncg = ncol >> 3;
    #pragma unroll
    for (int ks = 0; ks < 8; ks++) {
        u32 a[2][4];
        #pragma unroll
        for (int mt = 0; mt < 2; mt++) {
            u32 ap = As_addr + (u32)((mrow + mt * 16 + lq) * 272 + ks * 32 + lr * 4);
            a[mt][0] = lds32(ap);
            a[mt][1] = lds32(ap + 8 * 272);
            a[mt][2] = lds32(ap + 16);
            a[mt][3] = lds32(ap + 8 * 272 + 16);
        }
        u32 b0[4], b1[4];
        #pragma unroll
        for (int nt = 0; nt < 4; nt++)
            ldgB(b0[nt], b1[nt], Bp + (((ncg + nt) * 8 + ks) * 32 + lane));
        #pragma unroll
        for (int mt = 0; mt < 2; mt++)
            #pragma unroll
            for (int nt = 0; nt < 4; nt++)
                mma16(acc[mt][nt], a[mt], b0[nt], b1[nt]);
    }
}

// store K/Q tiles as fp16 row-major (stride 272B), rows < 49 only
__device__ __forceinline__ void store_rows_h(float acc[2][4][4], u32 dst_addr,
                                             const float* __restrict__ bias,
                                             int mrow, int ncol, int lane)
{
    const int lq = lane >> 2, lr = lane & 3;
    #pragma unroll
    for (int nt = 0; nt < 4; nt++) {
        const int c = ncol + nt * 8 + lr * 2;
        const float blo = __ldg(bias + c), bhi = __ldg(bias + c + 1);
        #pragma unroll
        for (int mt = 0; mt < 2; mt++) {
            const int r = mrow + mt * 16 + lq;
            if (r < 49)
                sts32(dst_addr + (u32)(r * 272 + c * 2),
                      pack_h2(acc[mt][nt][0] + blo, acc[mt][nt][1] + bhi));
            if (r + 8 < 49)
                sts32(dst_addr + (u32)((r + 8) * 272 + c * 2),
                      pack_h2(acc[mt][nt][2] + blo, acc[mt][nt][3] + bhi));
        }
    }
}

// store V transposed: VT[dim][token] fp16, stride 144B; row-pairs built via shfl_xor(4)
__device__ __forceinline__ void store_vT(float acc[2][4][4], u32 vt_addr,
                                         const float* __restrict__ bias,
                                         int mrow, int ncol, int lane)
{
    const int lq = lane >> 2, lr = lane & 3;
    const int odd = lq & 1;
    #pragma unroll
    for (int nt = 0; nt < 4; nt++) {
        const int c = ncol + nt * 8 + lr * 2;
        const float blo = __ldg(bias + c), bhi = __ldg(bias + c + 1);
        #pragma unroll
        for (int mt = 0; mt < 2; mt++) {
            #pragma unroll
            for (int half = 0; half < 2; half++) {
                const int r = mrow + mt * 16 + lq + half * 8;
                float v0 = acc[mt][nt][2 * half] + blo;
                float v1 = acc[mt][nt][2 * half + 1] + bhi;
                float o0 = __shfl_xor_sync(0xffffffffu, v0, 4);
                float o1 = __shfl_xor_sync(0xffffffffu, v1, 4);
                const int r0 = r & ~1;
                const int cc = c + odd;
                const u32 val = odd ? pack_h2(o1, v1) : pack_h2(v0, o0);
                const u32 addr = vt_addr + (u32)(cc * 144 + r0 * 2);
                if (r0 + 1 < 49)      sts32(addr, val);
                else if (r0 == 48)    sts16(addr, val);
            }
        }
    }
}

__global__ __launch_bounds__(TPB, 2)
void win_attn_kernel(const float* __restrict__ x,
                     const float* __restrict__ qkv_b,
                     const float* __restrict__ proj_b,
                     float* __restrict__ out)
{
    extern __shared__ char smem[];
    const u32 sbase = (u32)__cvta_generic_to_shared(smem);
    const u32 XQ_a = sbase + XQ_OFF;
    const u32 KS_a = sbase + KS_OFF;
    const u32 VT_a = sbase + VT_OFF;

    const int t    = threadIdx.x;
    const int wid  = t >> 5;
    const int lane = t & 31;
    const int lq   = lane >> 2, lr = lane & 3;
    const int mrow = (wid >> 2) * 32;
    const int ncol = (wid & 3) * 32;

    const int blk = blockIdx.x;
    const int b   = blk >> 6;
    const int win = blk & 63;
    const int wy  = win >> 3;
    const int wx  = win & 7;
    const long base = (((long)b * 56 + wy * 7) * 56 + wx * 7) * 128;

    // zero pads: K rows 49..55 (476 u32), VT tok-words 24..35 (1536), P col-words 28..31 (1024)
    for (int i = t; i < 476; i += TPB) {
        int rr = i / 68, cc = i - rr * 68;
        sts32(KS_a + (u32)((49 + rr) * 272 + cc * 4), 0u);
    }
    for (int i = t; i < 1536; i += TPB) {
        int d = i / 12, wd = i - d * 12;
        sts32(VT_a + (u32)(d * 144 + (24 + wd) * 4), 0u);
    }
    for (int i = t; i < 1024; i += TPB) {
        int h = i >> 8, rem = i & 255;
        int rr = rem >> 2, wd = rem & 3;
        sts32(sbase + P_OFF + (u32)(h * 9216 + rr * 144 + (28 + wd) * 4), 0u);
    }

    // stage X (49x128) as fp16 into XQ
    for (int idx = t; idx < 49 * 32; idx += TPB) {
        int r  = idx >> 5;
        int c4 = idx & 31;
        int iy = r / 7, ix = r - iy * 7;
        const float4 v = *(const float4*)(x + base + ((long)iy * 56 + ix) * 128 + c4 * 4);
        sts64u(XQ_a + (u32)(r * 272 + c4 * 8),
               pack_h2(v.x, v.y), pack_h2(v.z, v.w));
    }
    __syncthreads();

    // ---- K phase ----
    {
        float acc[2][4][4];
        #pragma unroll
        for (int a = 0; a < 2; a++) for (int q = 0; q < 4; q++) for (int c = 0; c < 4; c++) acc[a][q][c] = 0.f;
        gemm64h(XQ_a, g_B + 1 * 4096, mrow, ncol, lane, acc);
        store_rows_h(acc, KS_a, qkv_b + 128, mrow, ncol, lane);
    }
    // ---- V phase (transposed store) ----
    {
        float acc[2][4][4];
        #pragma unroll
        for (int a = 0; a < 2; a++) for (int q = 0; q < 4; q++) for (int c = 0; c < 4; c++) acc[a][q][c] = 0.f;
        gemm64h(XQ_a, g_B + 2 * 4096, mrow, ncol, lane, acc);
        store_vT(acc, VT_a, qkv_b + 256, mrow, ncol, lane);
    }
    // ---- Q phase (overwrites XQ after CTA-wide read completion) ----
    {
        float acc[2][4][4];
        #pragma unroll
        for (int a = 0; a < 2; a++) for (int q = 0; q < 4; q++) for (int c = 0; c < 4; c++) acc[a][q][c] = 0.f;
        gemm64h(XQ_a, g_B + 0 * 4096, mrow, ncol, lane, acc);
        __syncthreads();
        store_rows_h(acc, XQ_a, qkv_b, mrow, ncol, lane);
    }
    __syncthreads();

    // ================= attention: warp = (head h2, m-half msel) =================
    const int h2   = wid >> 1;
    const int msel = wid & 1;
    const int mra  = msel * 32;
    const u32 P_a  = sbase + P_OFF + (u32)(h2 * 9216);   // fp16 64 x 72 (144B stride)
    const int cls  = wid;                                // h2*2 + msel
    const float scale = 0.17677669529663687f;            // 32^-0.5

    // ---- S = Q·K^T  (m32 x n56, K=32 -> 2 k16 steps) ----
    float sacc[2][7][4];
    #pragma unroll
    for (int a = 0; a < 2; a++) for (int q = 0; q < 7; q++) for (int c = 0; c < 4; c++) sacc[a][q][c] = 0.f;
    #pragma unroll
    for (int ks = 0; ks < 2; ks++) {
        u32 a[2][4];
        #pragma unroll
        for (int mt = 0; mt < 2; mt++) {
            u32 ap = XQ_a + (u32)((mra + mt * 16 + lq) * 272 + h2 * 64 + ks * 32 + lr * 4);
            a[mt][0] = lds32(ap);
            a[mt][1] = lds32(ap + 8 * 272);
            a[mt][2] = lds32(ap + 16);
            a[mt][3] = lds32(ap + 8 * 272 + 16);
        }
        #pragma unroll
        for (int nt = 0; nt < 7; nt++) {
            u32 bp = KS_a + (u32)((nt * 8 + lq) * 272 + h2 * 64 + ks * 32 + lr * 4);
            u32 b0 = lds32(bp), b1 = lds32(bp + 16);
            mma16(sacc[0][nt], a[0], b0, b1);
            mma16(sacc[1][nt], a[1], b0, b1);
        }
    }

    // ---- softmax -> P (fp16, own region; no CTA barrier needed) ----
    float part[4] = {0.f, 0.f, 0.f, 0.f};
    #pragma unroll
    for (int nt = 0; nt < 7; nt++) {
        #pragma unroll
        for (int mt = 0; mt < 2; mt++) {
            const float4 gb = __ldg(g_bias4 + (cls * 14 + nt * 2 + mt) * 32 + lane);
            float p0 = __expf(fmaf(sacc[mt][nt][0], scale, gb.x));
            float p1 = __expf(fmaf(sacc[mt][nt][1], scale, gb.y));
            float p2 = __expf(fmaf(sacc[mt][nt][2], scale, gb.z));
            float p3 = __expf(fmaf(sacc[mt][nt][3], scale, gb.w));
            part[2 * mt]     += p0 + p1;
            part[2 * mt + 1] += p2 + p3;
            const int r0 = mra + mt * 16 + lq, col0 = nt * 8 + 2 * lr;
            sts32(P_a + (u32)(r0 * 144 + col0 * 2), pack_h2(p0, p1));
            sts32(P_a + (u32)((r0 + 8) * 144 + col0 * 2), pack_h2(p2, p3));
        }
    }
    __syncwarp();      // this warp's P rows are warp-private
    float inv[4];
    #pragma unroll
    for (int s = 0; s < 4; s++) {
        float l = part[s];
        l += __shfl_xor_sync(0xffffffffu, l, 1);
        l += __shfl_xor_sync(0xffffffffu, l, 2);
        inv[s] = 1.f / l;
    }

    // ---- O = P·V  (m32 x n32, K=64 -> 4 k16 steps; VT is B) ----
    float oacc[2][4][4];
    #pragma unroll
    for (int a = 0; a < 2; a++) for (int q = 0; q < 4; q++) for (int c = 0; c < 4; c++) oacc[a][q][c] = 0.f;
    #pragma unroll
    for (int ks = 0; ks < 4; ks++) {
        u32 a[2][4];
        #pragma unroll
        for (int mt = 0; mt < 2; mt++) {
            u32 ap = P_a + (u32)((mra + mt * 16 + lq) * 144 + ks * 32 + lr * 4);
            a[mt][0] = lds32(ap);
            a[mt][1] = lds32(ap + 8 * 144);
            a[mt][2] = lds32(ap + 16);
            a[mt][3] = lds32(ap + 8 * 144 + 16);
        }
        #pragma unroll
        for (int nt = 0; nt < 4; nt++) {
            u32 bp = VT_a + (u32)((h2 * 32 + nt * 8 + lq) * 144 + ks * 32 + lr * 4);
            u32 b0 = lds32(bp), b1 = lds32(bp + 16);
            mma16(oacc[0][nt], a[0], b0, b1);
            mma16(oacc[1][nt], a[1], b0, b1);
        }
    }

    // ---- O epilogue: normalize -> fp16 into XQ (own rows x own head-cols; no hazard) ----
    #pragma unroll
    for (int mt = 0; mt < 2; mt++) {
        #pragma unroll
        for (int nt = 0; nt < 4; nt++) {
            const int col = h2 * 32 + nt * 8 + 2 * lr;
            const u32 ra = XQ_a + (u32)((mra + mt * 16 + lq) * 272 + col * 2);
            sts32(ra, pack_h2(oacc[mt][nt][0] * inv[2 * mt],
                              oacc[mt][nt][1] * inv[2 * mt]));
            sts32(ra + 8 * 272, pack_h2(oacc[mt][nt][2] * inv[2 * mt + 1],
                                        oacc[mt][nt][3] * inv[2 * mt + 1]));
        }
    }
    __syncthreads();

    // ---- proj phase ----
    {
        float acc[2][4][4];
        #pragma unroll
        for (int a = 0; a < 2; a++) for (int q = 0; q < 4; q++) for (int c = 0; c < 4; c++) acc[a][q][c] = 0.f;
        gemm64h(XQ_a, g_B + 3 * 4096, mrow, ncol, lane, acc);

        #pragma unroll
        for (int nt = 0; nt < 4; nt++) {
            const int c = ncol + nt * 8 + lr * 2;
            const float blo = __ldg(proj_b + c), bhi = __ldg(proj_b + c + 1);
            #pragma unroll
            for (int mt = 0; mt < 2; mt++) {
                #pragma unroll
                for (int half = 0; half < 2; half++) {
                    const int r = mrow + mt * 16 + lq + half * 8;
                    if (r < 49) {
                        const int iy = r / 7, ix = r - iy * 7;
                        float2 v;
                        v.x = acc[mt][nt][2 * half + 0] + blo;
                        v.y = acc[mt][nt][2 * half + 1] + bhi;
                        *(float2*)(out + base + ((long)iy * 56 + ix) * 128 + c) = v;
                    }
                }
            }
        }
    }
}

extern "C" void kernel_launch(void* const* d_in, const int* in_sizes, int n_in,
                              void* d_out, int out_size)
{
    const float* x      = (const float*)d_in[0];
    const float* qkv_w  = (const float*)d_in[1];
    const float* qkv_b  = (const float*)d_in[2];
    const float* proj_w = (const float*)d_in[3];
    const float* proj_b = (const float*)d_in[4];
    const float* bt     = (const float*)d_in[5];
    float* out = (float*)d_out;

    repack<<<78, 256>>>(qkv_w, proj_w, bt);

    cudaFuncSetAttribute(win_attn_kernel,
                         cudaFuncAttributeMaxDynamicSharedMemorySize, SMB);
    win_attn_kernel<<<4096, TPB, SMB>>>(x, qkv_b, proj_b, out);
}

// round 15
// speedup vs baseline: 1.8501x; 1.0465x over previous
#include <cuda_runtime.h>

typedef unsigned int u32;
typedef unsigned long long u64;

#define TPB 256

// smem byte offsets (fp16 tiles)
#define XQ_OFF 0            // X -> Q -> attn-out: fp16 64 rows x 136 (272B stride)
#define KS_OFF 17408        // K: fp16 56 x 136 (pad rows 49..55 zeroed)
#define VT_OFF 32640        // V^T: fp16 128 dims x 72 toks (144B stride; toks 48..63 words zeroed)
#define SMB    51072

// pre-packed fp16 B fragments: [phase q,k,v,proj][ntile 16][kstep 8 (k16)][lane 32] -> u64(b0,b1)
__device__ u64 g_B[4 * 4096];
// expanded rel-pos bias in S-fragment order: [cls=h2*2+msel][fidx=nt*2+mt][lane] -> float4
__device__ float4 g_bias4[8 * 14 * 32];

// pack two f32 -> f16x2 (lo = first arg)
__device__ __forceinline__ u32 pack_h2(float lo, float hi) {
    u32 d; asm("cvt.rn.f16x2.f32 %0, %1, %2;" : "=r"(d) : "f"(hi), "f"(lo)); return d;
}

__global__ void repack(const float* __restrict__ qw, const float* __restrict__ pw,
                       const float* __restrict__ bt)
{
    int i = blockIdx.x * 256 + threadIdx.x;
    if (i < 16384) {
        int phase = i >> 12;
        int rem   = i & 4095;
        int nt    = rem >> 8;
        int ks    = (rem >> 5) & 7;
        int lane  = rem & 31;
        int n  = nt * 8 + (lane >> 2);
        int k0 = ks * 16 + (lane & 3) * 2;
        float f00, f01, f10, f11;
        if (phase < 3) {
            f00 = qw[(k0    ) * 384 + phase * 128 + n];
            f01 = qw[(k0 + 1) * 384 + phase * 128 + n];
            f10 = qw[(k0 + 8) * 384 + phase * 128 + n];
            f11 = qw[(k0 + 9) * 384 + phase * 128 + n];
        } else {
            f00 = pw[(k0    ) * 128 + n];
            f01 = pw[(k0 + 1) * 128 + n];
            f10 = pw[(k0 + 8) * 128 + n];
            f11 = pw[(k0 + 9) * 128 + n];
        }
        u32 b0 = pack_h2(f00, f01), b1 = pack_h2(f10, f11);
        g_B[i] = ((u64)b1 << 32) | (u64)b0;
    } else if (i < 16384 + 3584) {
        int j4   = i - 16384;              // float4 index
        int cls  = j4 / 448;               // h2*2 + msel
        int rem  = j4 - cls * 448;
        int fidx = rem >> 5;               // nt*2 + mt
        int lane = rem & 31;
        int msel = cls & 1;
        int h2 = cls >> 1;
        int nt = fidx >> 1, mt = fidx & 1;
        float v4[4];
        #pragma unroll
        for (int v = 0; v < 4; v++) {
            int row = msel * 32 + mt * 16 + (lane >> 2) + ((v >> 1) ? 8 : 0);
            int col = nt * 8 + (lane & 3) * 2 + (v & 1);
            if (col >= 49) v4[v] = -1e30f;     // padded key col -> p = 0
            else {
                int r = min(row, 48);
                int iy = r / 7, ix = r - iy * 7, jy = col / 7, jx = col - jy * 7;
                v4[v] = bt[((iy - jy + 6) * 13 + (ix - jx + 6)) * 4 + h2];
            }
        }
        g_bias4[j4] = make_float4(v4[0], v4[1], v4[2], v4[3]);
    }
}

// ---------------- helpers ----------------
__device__ __forceinline__ u32 lds32(u32 a) {
    u32 v; asm volatile("ld.shared.b32 %0, [%1];" : "=r"(v) : "r"(a)); return v;
}
__device__ __forceinline__ void sts32(u32 a, u32 v) {
    asm volatile("st.shared.b32 [%0], %1;" :: "r"(a), "r"(v) : "memory");
}
__device__ __forceinline__ void sts16(u32 a, u32 v) {
    asm volatile("st.shared.u16 [%0], %1;" :: "r"(a), "r"(v) : "memory");
}
__device__ __forceinline__ void sts64u(u32 a, u32 x, u32 y) {
    asm volatile("st.shared.v2.b32 [%0], {%1,%2};" :: "r"(a), "r"(x), "r"(y) : "memory");
}
__device__ __forceinline__ void ldgB(u32& b0, u32& b1, const u64* p) {
    asm volatile("ld.global.nc.v2.u32 {%0,%1}, [%2];" : "=r"(b0), "=r"(b1) : "l"(p));
}
__device__ __forceinline__ void mma16(float c[4], const u32 a[4], u32 b0, u32 b1) {
    asm("mma.sync.aligned.m16n8k16.row.col.f32.f16.f16.f32 "
        "{%0,%1,%2,%3},{%4,%5,%6,%7},{%8,%9},{%0,%1,%2,%3};"
        : "+f"(c[0]), "+f"(c[1]), "+f"(c[2]), "+f"(c[3])
        : "r"(a[0]), "r"(a[1]), "r"(a[2]), "r"(a[3]), "r"(b0), "r"(b1));
}

// D[64x128] = A[64x128]·B ; A = fp16 smem tile, stride 272B; warp tile m32 x n32
__device__ __forceinline__ void gemm64h(u32 As_addr, const u64* __restrict__ Bp,
                                        int mrow, int ncol, int lane, float acc[2][4][4])
{
    const int lq = lane >> 2, lr = lane & 3;
    const int ncg = ncol >> 3;
    #pragma unroll
    for (int ks = 0; ks < 8; ks++) {
        u32 a[2][4];
        #pragma unroll
        for (int mt = 0; mt < 2; mt++) {
            u32 ap = As_addr + (u32)((mrow + mt * 16 + lq) * 272 + ks * 32 + lr * 4);
            a[mt][0] = lds32(ap);
            a[mt][1] = lds32(ap + 8 * 272);
            a[mt][2] = lds32(ap + 16);
            a[mt][3] = lds32(ap + 8 * 272 + 16);
        }
        u32 b0[4], b1[4];
        #pragma unroll
        for (int nt = 0; nt < 4; nt++)
            ldgB(b0[nt], b1[nt], Bp + (((ncg + nt) * 8 + ks) * 32 + lane));
        #pragma unroll
        for (int mt = 0; mt < 2; mt++)
            #pragma unroll
            for (int nt = 0; nt < 4; nt++)
                mma16(acc[mt][nt], a[mt], b0[nt], b1[nt]);
    }
}

// store K/Q tiles as fp16 row-major (stride 272B), rows < 49 only
__device__ __forceinline__ void store_rows_h(float acc[2][4][4], u32 dst_addr,
                                             const float* __restrict__ bias,
                                             int mrow, int ncol, int lane)
{
    const int lq = lane >> 2, lr = lane & 3;
    #pragma unroll
    for (int nt = 0; nt < 4; nt++) {
        const int c = ncol + nt * 8 + lr * 2;
        const float blo = __ldg(bias + c), bhi = __ldg(bias + c + 1);
        #pragma unroll
        for (int mt = 0; mt < 2; mt++) {
            const int r = mrow + mt * 16 + lq;
            if (r < 49)
                sts32(dst_addr + (u32)(r * 272 + c * 2),
                      pack_h2(acc[mt][nt][0] + blo, acc[mt][nt][1] + bhi));
            if (r + 8 < 49)
                sts32(dst_addr + (u32)((r + 8) * 272 + c * 2),
                      pack_h2(acc[mt][nt][2] + blo, acc[mt][nt][3] + bhi));
        }
    }
}

// store V transposed: VT[dim][token] fp16, stride 144B; row-pairs built via shfl_xor(4)
__device__ __forceinline__ void store_vT(float acc[2][4][4], u32 vt_addr,
                                         const float* __restrict__ bias,
                                         int mrow, int ncol, int lane)
{
    const int lq = lane >> 2, lr = lane & 3;
    const int odd = lq & 1;
    #pragma unroll
    for (int nt = 0; nt < 4; nt++) {
        const int c = ncol + nt * 8 + lr * 2;
        const float blo = __ldg(bias + c), bhi = __ldg(bias + c + 1);
        #pragma unroll
        for (int mt = 0; mt < 2; mt++) {
            #pragma unroll
            for (int half = 0; half < 2; half++) {
                const int r = mrow + mt * 16 + lq + half * 8;
                float v0 = acc[mt][nt][2 * half] + blo;
                float v1 = acc[mt][nt][2 * half + 1] + bhi;
                float o0 = __shfl_xor_sync(0xffffffffu, v0, 4);
                float o1 = __shfl_xor_sync(0xffffffffu, v1, 4);
                const int r0 = r & ~1;
                const int cc = c + odd;
                const u32 val = odd ? pack_h2(o1, v1) : pack_h2(v0, o0);
                const u32 addr = vt_addr + (u32)(cc * 144 + r0 * 2);
                if (r0 + 1 < 49)      sts32(addr, val);
                else if (r0 == 48)    sts16(addr, val);
            }
        }
    }
}

__global__ __launch_bounds__(TPB, 2)
void win_attn_kernel(const float* __restrict__ x,
                     const float* __restrict__ qkv_b,
                     const float* __restrict__ proj_b,
                     float* __restrict__ out)
{
    extern __shared__ char smem[];
    const u32 sbase = (u32)__cvta_generic_to_shared(smem);
    const u32 XQ_a = sbase + XQ_OFF;
    const u32 KS_a = sbase + KS_OFF;
    const u32 VT_a = sbase + VT_OFF;

    const int t    = threadIdx.x;
    const int wid  = t >> 5;
    const int lane = t & 31;
    const int lq   = lane >> 2, lr = lane & 3;
    const int mrow = (wid >> 2) * 32;
    const int ncol = (wid & 3) * 32;

    const int blk = blockIdx.x;
    const int b   = blk >> 6;
    const int win = blk & 63;
    const int wy  = win >> 3;
    const int wx  = win & 7;
    const long base = (((long)b * 56 + wy * 7) * 56 + wx * 7) * 128;

    // zero pads: K rows 49..55 (476 u32), VT tok-words 24..31 (toks 48..63; tok48 rewritten by store_vT)
    for (int i = t; i < 476; i += TPB) {
        int rr = i / 68, cc = i - rr * 68;
        sts32(KS_a + (u32)((49 + rr) * 272 + cc * 4), 0u);
    }
    for (int i = t; i < 1024; i += TPB) {
        int d = i >> 3, wd = i & 7;
        sts32(VT_a + (u32)(d * 144 + (24 + wd) * 4), 0u);
    }

    // stage X (49x128) as fp16 into XQ
    for (int idx = t; idx < 49 * 32; idx += TPB) {
        int r  = idx >> 5;
        int c4 = idx & 31;
        int iy = r / 7, ix = r - iy * 7;
        const float4 v = *(const float4*)(x + base + ((long)iy * 56 + ix) * 128 + c4 * 4);
        sts64u(XQ_a + (u32)(r * 272 + c4 * 8),
               pack_h2(v.x, v.y), pack_h2(v.z, v.w));
    }
    __syncthreads();

    // ---- K phase ----
    {
        float acc[2][4][4];
        #pragma unroll
        for (int a = 0; a < 2; a++) for (int q = 0; q < 4; q++) for (int c = 0; c < 4; c++) acc[a][q][c] = 0.f;
        gemm64h(XQ_a, g_B + 1 * 4096, mrow, ncol, lane, acc);
        store_rows_h(acc, KS_a, qkv_b + 128, mrow, ncol, lane);
    }
    // ---- V phase (transposed store) ----
    {
        float acc[2][4][4];
        #pragma unroll
        for (int a = 0; a < 2; a++) for (int q = 0; q < 4; q++) for (int c = 0; c < 4; c++) acc[a][q][c] = 0.f;
        gemm64h(XQ_a, g_B + 2 * 4096, mrow, ncol, lane, acc);
        store_vT(acc, VT_a, qkv_b + 256, mrow, ncol, lane);
    }
    // ---- Q phase (overwrites XQ after CTA-wide read completion) ----
    {
        float acc[2][4][4];
        #pragma unroll
        for (int a = 0; a < 2; a++) for (int q = 0; q < 4; q++) for (int c = 0; c < 4; c++) acc[a][q][c] = 0.f;
        gemm64h(XQ_a, g_B + 0 * 4096, mrow, ncol, lane, acc);
        __syncthreads();
        store_rows_h(acc, XQ_a, qkv_b, mrow, ncol, lane);
    }
    __syncthreads();

    // ================= attention: warp = (head h2, m-half msel) =================
    const int h2   = wid >> 1;
    const int msel = wid & 1;
    const int mra  = msel * 32;
    const int cls  = wid;                                // h2*2 + msel
    const float scale = 0.17677669529663687f;            // 32^-0.5

    // ---- S = Q·K^T  (m32 x n56, K=32 -> 2 k16 steps) ----
    float sacc[2][7][4];
    #pragma unroll
    for (int a = 0; a < 2; a++) for (int q = 0; q < 7; q++) for (int c = 0; c < 4; c++) sacc[a][q][c] = 0.f;
    #pragma unroll
    for (int ks = 0; ks < 2; ks++) {
        u32 a[2][4];
        #pragma unroll
        for (int mt = 0; mt < 2; mt++) {
            u32 ap = XQ_a + (u32)((mra + mt * 16 + lq) * 272 + h2 * 64 + ks * 32 + lr * 4);
            a[mt][0] = lds32(ap);
            a[mt][1] = lds32(ap + 8 * 272);
            a[mt][2] = lds32(ap + 16);
            a[mt][3] = lds32(ap + 8 * 272 + 16);
        }
        #pragma unroll
        for (int nt = 0; nt < 7; nt++) {
            u32 bp = KS_a + (u32)((nt * 8 + lq) * 272 + h2 * 64 + ks * 32 + lr * 4);
            u32 b0 = lds32(bp), b1 = lds32(bp + 16);
            mma16(sacc[0][nt], a[0], b0, b1);
            mma16(sacc[1][nt], a[1], b0, b1);
        }
    }

    // ---- softmax -> P·V A-fragments directly in registers ----
    // m16n8k16 C fragment (row lq / lq+8, cols 2lr,2lr+1 of 8-col tile) maps exactly onto
    // the A fragment: tile nt = half of k16 group ks=nt>>1 (even nt -> a0/a1, odd -> a2/a3).
    u32 paf[2][4][4];
    paf[0][3][2] = paf[0][3][3] = paf[1][3][2] = paf[1][3][3] = 0u;   // cols 56..63 = 0
    float part[4] = {0.f, 0.f, 0.f, 0.f};
    #pragma unroll
    for (int nt = 0; nt < 7; nt++) {
        #pragma unroll
        for (int mt = 0; mt < 2; mt++) {
            const float4 gb = __ldg(g_bias4 + (cls * 14 + nt * 2 + mt) * 32 + lane);
            float p0 = __expf(fmaf(sacc[mt][nt][0], scale, gb.x));
            float p1 = __expf(fmaf(sacc[mt][nt][1], scale, gb.y));
            float p2 = __expf(fmaf(sacc[mt][nt][2], scale, gb.z));
            float p3 = __expf(fmaf(sacc[mt][nt][3], scale, gb.w));
            part[2 * mt]     += p0 + p1;
            part[2 * mt + 1] += p2 + p3;
            const int ks = nt >> 1;
            if ((nt & 1) == 0) {
                paf[mt][ks][0] = pack_h2(p0, p1);
                paf[mt][ks][1] = pack_h2(p2, p3);
            } else {
                paf[mt][ks][2] = pack_h2(p0, p1);
                paf[mt][ks][3] = pack_h2(p2, p3);
            }
        }
    }
    float inv[4];
    #pragma unroll
    for (int s = 0; s < 4; s++) {
        float l = part[s];
        l += __shfl_xor_sync(0xffffffffu, l, 1);
        l += __shfl_xor_sync(0xffffffffu, l, 2);
        inv[s] = 1.f / l;
    }

    // ---- O = P·V  (m32 x n32, K=64 -> 4 k16 steps; P from registers, VT is B) ----
    float oacc[2][4][4];
    #pragma unroll
    for (int a = 0; a < 2; a++) for (int q = 0; q < 4; q++) for (int c = 0; c < 4; c++) oacc[a][q][c] = 0.f;
    #pragma unroll
    for (int ks = 0; ks < 4; ks++) {
        #pragma unroll
        for (int nt = 0; nt < 4; nt++) {
            u32 bp = VT_a + (u32)((h2 * 32 + nt * 8 + lq) * 144 + ks * 32 + lr * 4);
            u32 b0 = lds32(bp), b1 = lds32(bp + 16);
            mma16(oacc[0][nt], paf[0][ks], b0, b1);
            mma16(oacc[1][nt], paf[1][ks], b0, b1);
        }
    }

    // ---- O epilogue: normalize -> fp16 into XQ (own rows x own head-cols; no hazard) ----
    #pragma unroll
    for (int mt = 0; mt < 2; mt++) {
        #pragma unroll
        for (int nt = 0; nt < 4; nt++) {
            const int col = h2 * 32 + nt * 8 + 2 * lr;
            const u32 ra = XQ_a + (u32)((mra + mt * 16 + lq) * 272 + col * 2);
            sts32(ra, pack_h2(oacc[mt][nt][0] * inv[2 * mt],
                              oacc[mt][nt][1] * inv[2 * mt]));
            sts32(ra + 8 * 272, pack_h2(oacc[mt][nt][2] * inv[2 * mt + 1],
                                        oacc[mt][nt][3] * inv[2 * mt + 1]));
        }
    }
    __syncthreads();

    // ---- proj phase ----
    {
        float acc[2][4][4];
        #pragma unroll
        for (int a = 0; a < 2; a++) for (int q = 0; q < 4; q++) for (int c = 0; c < 4; c++) acc[a][q][c] = 0.f;
        gemm64h(XQ_a, g_B + 3 * 4096, mrow, ncol, lane, acc);

        #pragma unroll
        for (int nt = 0; nt < 4; nt++) {
            const int c = ncol + nt * 8 + lr * 2;
            const float blo = __ldg(proj_b + c), bhi = __ldg(proj_b + c + 1);
            #pragma unroll
            for (int mt = 0; mt < 2; mt++) {
                #pragma unroll
                for (int half = 0; half < 2; half++) {
                    const int r = mrow + mt * 16 + lq + half * 8;
                    if (r < 49) {
                        const int iy = r / 7, ix = r - iy * 7;
                        float2 v;
                        v.x = acc[mt][nt][2 * half + 0] + blo;
                        v.y = acc[mt][nt][2 * half + 1] + bhi;
                        *(float2*)(out + base + ((long)iy * 56 + ix) * 128 + c) = v;
                    }
                }
            }
        }
    }
}

extern "C" void kernel_launch(void* const* d_in, const int* in_sizes, int n_in,
                              void* d_out, int out_size)
{
    const float* x      = (const float*)d_in[0];
    const float* qkv_w  = (const float*)d_in[1];
    const float* qkv_b  = (const float*)d_in[2];
    const float* proj_w = (const float*)d_in[3];
    const float* proj_b = (const float*)d_in[4];
    const float* bt     = (const float*)d_in[5];
    float* out = (float*)d_out;

    repack<<<78, 256>>>(qkv_w, proj_w, bt);

    cudaFuncSetAttribute(win_attn_kernel,
                         cudaFuncAttributeMaxDynamicSharedMemorySize, SMB);
    win_attn_kernel<<<4096, TPB, SMB>>>(x, qkv_b, proj_b, out);
}